// round 5
// baseline (speedup 1.0000x reference)
#include <cuda_runtime.h>
#include <math.h>

// Problem constants
#define SS 3       // REFINE_LAYERS
#define BB 32      // batch
#define NN 2000    // priors
#define LL 4       // max lanes
#define DD 78      // 2 + 4 + 72
#define NP 72      // num points offsets
#define CH 40      // priors staged per chunk
#define NCH (NN / CH)   // 50

// Scratch (device globals; no allocation allowed)
__device__ float2   g_clslog[2][SS][BB][NN];
__device__ int      g_rows[2][SS][BB][LL];
__device__ float    g_inst[2][NN];
__device__ float    g_regpart[2][SS][BB][LL];
__device__ float    g_ioupart[2][SS][BB][LL];
__device__ unsigned g_done;

// ---------------------------------------------------------------------------
// Kernel 1: cost + greedy assignment fused. One block per (branch, s, b).
// Cost matrix lives in shared (4 x 2000); 50 chunks of 40 prior rows staged
// into sp (stride 84 -> conflict-free float4 LDS). Then 4 greedy argmin
// passes over shared cost, tie-break lowest index (jnp.argmin).
// ---------------------------------------------------------------------------
__global__ void __launch_bounds__(320) k_costassign(const float* __restrict__ pA,
                                                    const float* __restrict__ pB,
                                                    const float* __restrict__ gt) {
    __shared__ float scost[LL][NN];   // 32000 B
    __shared__ float sp[CH][84];      // 13440 B
    __shared__ float sq[LL][NP];      // gt offsets * (1/799)
    __shared__ float sraw[LL][4];     // raw gt dims 2..5
    __shared__ float swv[10];
    __shared__ int   swi[10];
    __shared__ int   chosen[LL];
    const int tid = threadIdx.x;

    int b = blockIdx.x % BB; int t = blockIdx.x / BB;
    int s = t % SS; int br = t / SS;

    if (blockIdx.x == 0 && tid == 0) g_done = 0;   // reset for kernel 2

    // gt staging (312 values)
    for (int i = tid; i < LL * DD; i += 320) {
        int l = i / DD, d = i % DD;
        float v = gt[b * LL * DD + i];
        if (d >= 6)      sq[l][d - 6]   = v * (1.0f / 799.0f);
        else if (d >= 2) sraw[l][d - 2] = v;
    }
    __syncthreads();

    const float* pred = (br ? pB : pA) + ((size_t)((s * BB + b) * NN)) * DD;

    for (int ch = 0; ch < NCH; ch++) {
        int n0 = ch * CH;
        const float2* p2 = (const float2*)(pred + (size_t)n0 * DD);
        for (int i = tid; i < CH * DD / 2; i += 320) {   // 1560 float2
            float2 v = p2[i];
            int e = 2 * i;
            int r = e / DD, c = e % DD;
            *(float2*)&sp[r][2 + c] = v;     // (84r + 2 + c) even -> 8B aligned
        }
        __syncthreads();
        if (tid < CH * LL) {
            int pr = tid >> 2, l = tid & 3;
            float p0 = sp[pr][2], p1 = sp[pr][3];
            float mx  = fmaxf(p0, p1);
            float e0  = __expf(p0 - mx), e1 = __expf(p1 - mx);
            float sum = e0 + e1;
            float lse = mx + __logf(sum);
            float score = __fdividef(e1, sum);

            float4 g4 = *(const float4*)&sp[pr][4];   // dims 2..5
            float4 t4 = *(const float4*)&sraw[l][0];
            float geo = fabsf(g4.x - t4.x) + fabsf(g4.y - t4.y)
                      + fabsf(g4.z - t4.z) + fabsf(g4.w - t4.w);

            float off = 0.0f;
            #pragma unroll
            for (int k = 0; k < NP / 4; k++) {
                float4 a = *(const float4*)&sp[pr][8 + 4 * k];
                float4 q = *(const float4*)&sq[l][4 * k];
                off += fabsf(a.x - q.x) + fabsf(a.y - q.y)
                     + fabsf(a.z - q.z) + fabsf(a.w - q.w);
            }
            scost[l][n0 + pr] = geo + off * (1.0f / 72.0f) - score;
            if (l == 0)
                g_clslog[br][s][b][n0 + pr] = make_float2(p0 - lse, p1 - lse);
        }
        __syncthreads();   // protect sp reuse; after last iter protects scost
    }

    // greedy assignment without replacement (10 warps)
    const int wib = tid >> 5, lane = tid & 31;
    for (int l = 0; l < LL; l++) {
        float best = INFINITY; int bi = NN;
        for (int n = tid; n < NN; n += 320) {
            bool used = false;
            #pragma unroll
            for (int j = 0; j < 3; j++) used |= (j < l) && (chosen[j] == n);
            float v = used ? INFINITY : scost[l][n];
            if (v < best) { best = v; bi = n; }   // ascending n -> first idx tie
        }
        #pragma unroll
        for (int o = 16; o; o >>= 1) {
            float ov = __shfl_xor_sync(0xffffffffu, best, o);
            int   oi = __shfl_xor_sync(0xffffffffu, bi,   o);
            if (ov < best || (ov == best && oi < bi)) { best = ov; bi = oi; }
        }
        if (lane == 0) { swv[wib] = best; swi[wib] = bi; }
        __syncthreads();
        if (tid == 0) {
            float bv = swv[0]; int bix = swi[0];
            #pragma unroll
            for (int w = 1; w < 10; w++) {
                if (swv[w] < bv || (swv[w] == bv && swi[w] < bix)) {
                    bv = swv[w]; bix = swi[w];
                }
            }
            chosen[l] = bix; g_rows[br][s][b][l] = bix;
        }
        __syncthreads();
    }
}

// ---------------------------------------------------------------------------
// Kernel 2: cls (blocks 0-15) + matched (blocks 16-111), then the LAST block
// to finish runs the finalize phase (median via warp-aggregated radix select
// + weighted sum). g_done counter reset by kernel 1.
// ---------------------------------------------------------------------------
__global__ void __launch_bounds__(256) k_rest(const float* __restrict__ pA,
                                              const float* __restrict__ pB,
                                              const float* __restrict__ gt,
                                              const float* __restrict__ diff,
                                              float* __restrict__ out) {
    __shared__ int      srows[SS * BB * LL];   // cls staging
    __shared__ unsigned su[NN];                // radix keys
    __shared__ int      hist[256];
    __shared__ int      s_sel, s_k;
    __shared__ float    s_med[2];
    __shared__ float    sred[256];
    __shared__ int      s_last;
    const int tid = threadIdx.x;
    const int lane = tid & 31;

    if (blockIdx.x < 16) {
        // ---- cls part ----
        int br = blockIdx.x >> 3;
        int n  = (blockIdx.x & 7) * 256 + tid;

        const int* rsrc = &g_rows[br][0][0][0];
        for (int i = tid; i < SS * BB * LL; i += 256) srows[i] = rsrc[i];
        __syncthreads();

        if (n < NN) {
            const float2* lpbase = &g_clslog[br][0][0][0];
            float acc = 0.0f;
            #pragma unroll 4
            for (int sb = 0; sb < SS * BB; sb++) {
                float2 lp = lpbase[sb * NN + n];
                const int* r = &srows[sb * 4];
                bool matched = (r[0] == n) | (r[1] == n) | (r[2] == n) | (r[3] == n);
                float logpt = matched ? lp.y : lp.x;
                float pt = __expf(logpt);
                float a = matched ? 0.9f : 0.1f;
                float om = 1.0f - pt;
                acc += -a * om * om * logpt;
            }
            g_inst[br][n] = acc * (1.0f / 96.0f) * 2.0f;  // /(B*S), * CLS_W
        }
    } else {
        // ---- matched part: one warp per (br,s,b,l) ----
        int wib = tid >> 5;
        int id = (blockIdx.x - 16) * 8 + wib;   // [0, 768)
        int l = id % LL; int t = id / LL;
        int b = t % BB;  t /= BB;
        int s = t % SS;  int br = t / SS;

        int r = g_rows[br][s][b][l];
        const float* pm = (br ? pB : pA) + ((size_t)((s * BB + b) * NN + r)) * DD;
        const float* tg = gt + (b * LL + l) * DD;

        float sl = 0.0f;
        if (lane < 4) {
            const float scv[4] = {71.0f, 799.0f, 180.0f, 71.0f};
            float d = pm[2 + lane] * scv[lane] - tg[2 + lane] * scv[lane];
            float ad = fabsf(d);
            sl = (ad < 1.0f) ? 0.5f * d * d : ad - 0.5f;
        }
        float ovr = 0.0f, uni = 0.0f;
        #pragma unroll
        for (int jj = 0; jj < 3; jj++) {
            int j = lane + jj * 32;
            if (j < NP) {
                float rp = pm[6 + j] * 799.0f;
                float rt = tg[6 + j];
                bool inv = (rt < 0.0f) || (rt >= 800.0f);
                float o = fminf(rp + 15.0f, rt + 15.0f) - fmaxf(rp - 15.0f, rt - 15.0f);
                float u = fmaxf(rp + 15.0f, rt + 15.0f) - fminf(rp - 15.0f, rt - 15.0f);
                if (!inv) { ovr += o; uni += u; }
            }
        }
        #pragma unroll
        for (int o = 16; o; o >>= 1) {
            sl  += __shfl_xor_sync(0xffffffffu, sl,  o);
            ovr += __shfl_xor_sync(0xffffffffu, ovr, o);
            uni += __shfl_xor_sync(0xffffffffu, uni, o);
        }
        if (lane == 0) {
            float iou = ovr / (uni + 1e-9f);
            g_regpart[br][s][b][l] = (sl * 0.25f) / (float)LL;
            g_ioupart[br][s][b][l] = (1.0f - iou) / (float)LL;
        }
    }

    // ---- last-block-done gate ----
    __syncthreads();
    if (tid == 0) {
        __threadfence();
        unsigned old = atomicAdd(&g_done, 1u);
        s_last = (old == 111u);
        if (s_last) __threadfence();   // acquire side
    }
    __syncthreads();
    if (!s_last) return;

    // ================= finalize phase (one block, 256 threads) ==============
    // step 1: per-(branch,l) deterministic reduce + inst scatter
    if (tid < 2 * LL) {
        int br = tid >> 2, l = tid & 3;
        const float* rp = &g_regpart[br][0][0][0];
        const float* ip = &g_ioupart[br][0][0][0];
        float rs = 0.0f, is = 0.0f;
        for (int sb = 0; sb < SS * BB; sb++) {
            rs += rp[sb * LL + l];
            is += ip[sb * LL + l];
        }
        rs *= (1.0f / 96.0f);
        is *= (1.0f / 96.0f);
        int row = g_rows[br][SS - 1][BB - 1][l];
        g_inst[br][row] += rs * 0.5f + is * 2.0f;  // REG_W, IOU_W
    }
    __syncthreads();

    // step 2: order-preserving uint keys of x = instA - instB
    for (int n = tid; n < NN; n += 256) {
        float x = g_inst[0][n] - g_inst[1][n];
        unsigned u = __float_as_uint(x);
        su[n] = (u & 0x80000000u) ? ~u : (u | 0x80000000u);
    }
    __syncthreads();

    // step 3: exact radix select for ranks 999 & 1000 (warp-aggregated hist)
    for (int rsel = 0; rsel < 2; rsel++) {
        int k = 999 + rsel;
        unsigned prefix = 0;
        for (int shift = 24; shift >= 0; shift -= 8) {
            hist[tid] = 0;
            __syncthreads();
            unsigned mask = (shift == 24) ? 0u : (0xFFFFFFFFu << (shift + 8));
            #pragma unroll
            for (int it = 0; it < 8; it++) {
                int i = tid + it * 256;
                int bin = 256;
                if (i < NN) {
                    unsigned u = su[i];
                    if ((u & mask) == prefix) bin = (int)((u >> shift) & 255);
                }
                unsigned mm = __match_any_sync(0xffffffffu, bin);
                if (bin < 256 && lane == (__ffs(mm) - 1))
                    atomicAdd(&hist[bin], __popc(mm));
            }
            __syncthreads();
            if (tid < 32) {
                int base = tid * 8, ssum = 0;
                int c[8];
                #pragma unroll
                for (int j = 0; j < 8; j++) { c[j] = hist[base + j]; ssum += c[j]; }
                int run = ssum;
                #pragma unroll
                for (int o = 1; o < 32; o <<= 1) {
                    int v = __shfl_up_sync(0xffffffffu, run, o);
                    if (tid >= o) run += v;
                }
                int excl = run - ssum;
                if (k >= excl && k < run) {
                    int acc2 = excl;
                    #pragma unroll
                    for (int j = 0; j < 8; j++) {
                        if (k < acc2 + c[j]) { s_sel = base + j; s_k = k - acc2; break; }
                        acc2 += c[j];
                    }
                }
            }
            __syncthreads();
            prefix |= ((unsigned)s_sel) << shift;
            k = s_k;
        }
        if (tid == 0) {
            unsigned u = prefix;
            s_med[rsel] = (u & 0x80000000u) ? __uint_as_float(u ^ 0x80000000u)
                                            : __uint_as_float(~u);
        }
        __syncthreads();
    }
    float delta = 0.5f * (s_med[0] + s_med[1]);

    // step 4: total = sum (1-dm)*(A - d/2) + dm*(B + d/2)
    float acc = 0.0f;
    for (int n = tid; n < NN; n += 256) {
        float dm = (diff[n] + diff[NN + n] + diff[2 * NN + n]) * (1.0f / 3.0f);
        acc += (1.0f - dm) * (g_inst[0][n] - 0.5f * delta)
             + dm * (g_inst[1][n] + 0.5f * delta);
    }
    sred[tid] = acc;
    __syncthreads();
    for (int o = 128; o; o >>= 1) {
        if (tid < o) sred[tid] += sred[tid + o];
        __syncthreads();
    }
    if (tid == 0) out[0] = sred[0];
}

// ---------------------------------------------------------------------------
extern "C" void kernel_launch(void* const* d_in, const int* in_sizes, int n_in,
                              void* d_out, int out_size) {
    const float* pA   = (const float*)d_in[0];  // predictions_fir [S,B,N,D]
    const float* pB   = (const float*)d_in[1];  // predictions_sec [S,B,N,D]
    const float* gt   = (const float*)d_in[2];  // gt_lane [B,L,D]
    const float* diff = (const float*)d_in[3];  // diff [S,N]
    float* out = (float*)d_out;

    k_costassign<<<2 * SS * BB, 320>>>(pA, pB, gt);        // 192 blocks
    k_rest<<<16 + 96, 256>>>(pA, pB, gt, diff, out);       // 112 blocks
}

// round 6
// speedup vs baseline: 2.0040x; 2.0040x over previous
#include <cuda_runtime.h>
#include <math.h>

// Problem constants
#define SS 3       // REFINE_LAYERS
#define BB 32      // batch
#define NN 2000    // priors
#define LL 4       // max lanes
#define DD 78      // 2 + 4 + 72
#define NP 72      // num points offsets
#define PRI 80     // priors per k_cost block

// Scratch (device globals; no allocation allowed)
__device__ float  g_cost[2][SS][BB][LL][NN];   // transposed: coalesced argmin reads
__device__ float2 g_clslog[2][SS][BB][NN];
__device__ int    g_rows[2][SS][BB][LL];
__device__ float  g_inst[2][NN];
__device__ float  g_regpart[2][SS][BB][LL];
__device__ float  g_ioupart[2][SS][BB][LL];

// ---------------------------------------------------------------------------
// Kernel 1: cost matrix + per-prior log-softmax.
// Thread-per-(prior, gt-lane): block stages 80 prior rows + gt in shared,
// each thread serially accumulates |p - t| with float4 shared loads.
// ---------------------------------------------------------------------------
__global__ void __launch_bounds__(320) k_cost(const float* __restrict__ pA,
                                              const float* __restrict__ pB,
                                              const float* __restrict__ gt) {
    __shared__ float sp[PRI][84];   // prediction rows, dims at [2..79]
    __shared__ float sq[LL][NP];    // gt offsets * (1/799)
    __shared__ float sraw[LL][4];   // raw gt dims 2..5
    const int tid = threadIdx.x;

    int chunk = blockIdx.x % (NN / PRI);   // 25 chunks
    int t = blockIdx.x / (NN / PRI);
    int b = t % BB;  t /= BB;
    int s = t % SS;  int br = t / SS;
    int n0 = chunk * PRI;

    for (int i = tid; i < LL * DD; i += 320) {
        int l = i / DD, d = i % DD;
        float v = gt[b * LL * DD + i];
        if (d >= 6)      sq[l][d - 6]   = v * (1.0f / 799.0f);
        else if (d >= 2) sraw[l][d - 2] = v;
    }
    const float2* p2 = (const float2*)((br ? pB : pA)
                     + ((size_t)((s * BB + b) * NN + n0)) * DD);
    for (int i = tid; i < PRI * DD / 2; i += 320) {  // 3120
        float2 v = p2[i];
        int e = 2 * i;
        int r = e / DD, c = e % DD;
        *(float2*)&sp[r][2 + c] = v;    // (84r + 2 + c) even -> 8B aligned
    }
    __syncthreads();

    int pr = tid >> 2, l = tid & 3;
    float p0 = sp[pr][2], p1 = sp[pr][3];
    float mx  = fmaxf(p0, p1);
    float e0  = __expf(p0 - mx), e1 = __expf(p1 - mx);
    float sum = e0 + e1;
    float lse = mx + __logf(sum);
    float score = __fdividef(e1, sum);

    float4 g4 = *(const float4*)&sp[pr][4];    // dims 2..5
    float4 t4 = *(const float4*)&sraw[l][0];
    float geo = fabsf(g4.x - t4.x) + fabsf(g4.y - t4.y)
              + fabsf(g4.z - t4.z) + fabsf(g4.w - t4.w);

    float off = 0.0f;
    #pragma unroll
    for (int k = 0; k < NP / 4; k++) {
        float4 a = *(const float4*)&sp[pr][8 + 4 * k];
        float4 q = *(const float4*)&sq[l][4 * k];
        off += fabsf(a.x - q.x) + fabsf(a.y - q.y)
             + fabsf(a.z - q.z) + fabsf(a.w - q.w);
    }
    g_cost[br][s][b][l][n0 + pr] = geo + off * (1.0f / 72.0f) - score;
    if (l == 0)
        g_clslog[br][s][b][n0 + pr] = make_float2(p0 - lse, p1 - lse);
}

// ---------------------------------------------------------------------------
// Kernel 2: greedy assignment without replacement, per (branch,s,b).
// L=4 sequential argmins over N; tie-break = lowest index (jnp.argmin).
// ---------------------------------------------------------------------------
__global__ void __launch_bounds__(256) k_assign() {
    int b = blockIdx.x % BB; int t = blockIdx.x / BB;
    int s = t % SS; int br = t / SS;
    const int wib = threadIdx.x >> 5, lane = threadIdx.x & 31;

    __shared__ float swv[8];
    __shared__ int   swi[8];
    __shared__ int   chosen[LL];

    for (int l = 0; l < LL; l++) {
        const float* cost = &g_cost[br][s][b][l][0];
        float best = INFINITY; int bi = NN;
        for (int n = threadIdx.x; n < NN; n += 256) {
            bool used = false;
            #pragma unroll
            for (int j = 0; j < 3; j++) used |= (j < l) && (chosen[j] == n);
            float v = used ? INFINITY : __ldg(&cost[n]);
            if (v < best) { best = v; bi = n; }   // ascending n -> first idx on tie
        }
        #pragma unroll
        for (int o = 16; o; o >>= 1) {
            float ov = __shfl_xor_sync(0xffffffffu, best, o);
            int   oi = __shfl_xor_sync(0xffffffffu, bi,   o);
            if (ov < best || (ov == best && oi < bi)) { best = ov; bi = oi; }
        }
        if (lane == 0) { swv[wib] = best; swi[wib] = bi; }
        __syncthreads();
        if (threadIdx.x == 0) {
            float bv = swv[0]; int bix = swi[0];
            #pragma unroll
            for (int w = 1; w < 8; w++) {
                if (swv[w] < bv || (swv[w] == bv && swi[w] < bix)) {
                    bv = swv[w]; bix = swi[w];
                }
            }
            chosen[l] = bix; g_rows[br][s][b][l] = bix;
        }
        __syncthreads();
    }
}

// ---------------------------------------------------------------------------
// Kernel 3 (fused): blocks 0-15 = focal cls loss; blocks 16-111 = matched
// smooth-L1 + line-IoU partials (8 warps/block, one item each).
// ---------------------------------------------------------------------------
__global__ void __launch_bounds__(256) k_clsmatched(const float* __restrict__ pA,
                                                    const float* __restrict__ pB,
                                                    const float* __restrict__ gt) {
    if (blockIdx.x < 16) {
        __shared__ int srows[SS * BB * LL];   // 384
        int br = blockIdx.x >> 3;
        int n  = (blockIdx.x & 7) * 256 + threadIdx.x;

        const int* rsrc = &g_rows[br][0][0][0];
        for (int i = threadIdx.x; i < SS * BB * LL; i += 256) srows[i] = rsrc[i];
        __syncthreads();
        if (n >= NN) return;

        const float2* lpbase = &g_clslog[br][0][0][0];
        float acc = 0.0f;
        #pragma unroll 4
        for (int sb = 0; sb < SS * BB; sb++) {
            float2 lp = lpbase[sb * NN + n];
            const int* r = &srows[sb * 4];
            bool matched = (r[0] == n) | (r[1] == n) | (r[2] == n) | (r[3] == n);
            float logpt = matched ? lp.y : lp.x;
            float pt = __expf(logpt);
            float a = matched ? 0.9f : 0.1f;
            float om = 1.0f - pt;
            acc += -a * om * om * logpt;
        }
        g_inst[br][n] = acc * (1.0f / 96.0f) * 2.0f;  // /(B*S), * CLS_W
    } else {
        int wib = threadIdx.x >> 5, lane = threadIdx.x & 31;
        int id = (blockIdx.x - 16) * 8 + wib;   // [0, 768)
        int l = id % LL; int t = id / LL;
        int b = t % BB;  t /= BB;
        int s = t % SS;  int br = t / SS;

        int r = g_rows[br][s][b][l];
        const float* pm = (br ? pB : pA) + ((size_t)((s * BB + b) * NN + r)) * DD;
        const float* tg = gt + (b * LL + l) * DD;

        float sl = 0.0f;
        if (lane < 4) {
            const float scv[4] = {71.0f, 799.0f, 180.0f, 71.0f};
            float d = pm[2 + lane] * scv[lane] - tg[2 + lane] * scv[lane];
            float ad = fabsf(d);
            sl = (ad < 1.0f) ? 0.5f * d * d : ad - 0.5f;
        }
        float ovr = 0.0f, uni = 0.0f;
        #pragma unroll
        for (int jj = 0; jj < 3; jj++) {
            int j = lane + jj * 32;
            if (j < NP) {
                float rp = pm[6 + j] * 799.0f;
                float rt = tg[6 + j];
                bool inv = (rt < 0.0f) || (rt >= 800.0f);
                float o = fminf(rp + 15.0f, rt + 15.0f) - fmaxf(rp - 15.0f, rt - 15.0f);
                float u = fmaxf(rp + 15.0f, rt + 15.0f) - fminf(rp - 15.0f, rt - 15.0f);
                if (!inv) { ovr += o; uni += u; }
            }
        }
        #pragma unroll
        for (int o = 16; o; o >>= 1) {
            sl  += __shfl_xor_sync(0xffffffffu, sl,  o);
            ovr += __shfl_xor_sync(0xffffffffu, ovr, o);
            uni += __shfl_xor_sync(0xffffffffu, uni, o);
        }
        if (lane == 0) {
            float iou = ovr / (uni + 1e-9f);
            g_regpart[br][s][b][l] = (sl * 0.25f) / (float)LL;
            g_ioupart[br][s][b][l] = (1.0f - iou) / (float)LL;
        }
    }
}

// ---------------------------------------------------------------------------
// Kernel 4: finalize. reg/iou reduce + scatter, exact radix-select median
// with warp-aggregated histogram (keys cluster near 0 -> naive atomics
// serialize; match_any makes it ~1 atomic per warp per bin), weighted sum.
// ---------------------------------------------------------------------------
__global__ void __launch_bounds__(1024) k_final(const float* __restrict__ diff,
                                                float* __restrict__ out) {
    __shared__ unsigned su[NN];
    __shared__ int hist[256];
    __shared__ int s_sel, s_k;
    __shared__ float s_med[2];
    __shared__ float sred[1024];
    int tid = threadIdx.x;
    int lane = tid & 31;

    // step 1: per-(branch,l) deterministic reduce + inst scatter
    if (tid < 2 * LL) {
        int br = tid >> 2, l = tid & 3;
        const float* rp = &g_regpart[br][0][0][0];
        const float* ip = &g_ioupart[br][0][0][0];
        float rs = 0.0f, is = 0.0f;
        for (int sb = 0; sb < SS * BB; sb++) {
            rs += rp[sb * LL + l];
            is += ip[sb * LL + l];
        }
        rs *= (1.0f / 96.0f);
        is *= (1.0f / 96.0f);
        int row = g_rows[br][SS - 1][BB - 1][l];
        g_inst[br][row] += rs * 0.5f + is * 2.0f;  // REG_W, IOU_W
    }
    __syncthreads();

    // step 2: order-preserving uint keys of x = instA - instB
    for (int n = tid; n < NN; n += 1024) {
        float x = g_inst[0][n] - g_inst[1][n];
        unsigned u = __float_as_uint(x);
        su[n] = (u & 0x80000000u) ? ~u : (u | 0x80000000u);
    }
    __syncthreads();

    // step 3: exact radix select for ranks 999 and 1000
    for (int rsel = 0; rsel < 2; rsel++) {
        int k = 999 + rsel;
        unsigned prefix = 0;
        for (int shift = 24; shift >= 0; shift -= 8) {
            if (tid < 256) hist[tid] = 0;
            __syncthreads();
            unsigned mask = (shift == 24) ? 0u : (0xFFFFFFFFu << (shift + 8));
            #pragma unroll
            for (int it = 0; it < 2; it++) {
                int i = tid + it * 1024;
                int bin = 256;   // sentinel: inactive
                if (i < NN) {
                    unsigned u = su[i];
                    if ((u & mask) == prefix) bin = (int)((u >> shift) & 255);
                }
                unsigned mm = __match_any_sync(0xffffffffu, bin);
                if (bin < 256 && lane == (__ffs(mm) - 1))
                    atomicAdd(&hist[bin], __popc(mm));
            }
            __syncthreads();
            if (tid < 32) {
                int base = tid * 8, ssum = 0;
                int c[8];
                #pragma unroll
                for (int j = 0; j < 8; j++) { c[j] = hist[base + j]; ssum += c[j]; }
                int run = ssum;
                #pragma unroll
                for (int o = 1; o < 32; o <<= 1) {
                    int v = __shfl_up_sync(0xffffffffu, run, o);
                    if (tid >= o) run += v;
                }
                int excl = run - ssum;
                if (k >= excl && k < run) {
                    int acc2 = excl;
                    #pragma unroll
                    for (int j = 0; j < 8; j++) {
                        if (k < acc2 + c[j]) { s_sel = base + j; s_k = k - acc2; break; }
                        acc2 += c[j];
                    }
                }
            }
            __syncthreads();
            prefix |= ((unsigned)s_sel) << shift;
            k = s_k;
            __syncthreads();
        }
        if (tid == 0) {
            unsigned u = prefix;
            s_med[rsel] = (u & 0x80000000u) ? __uint_as_float(u ^ 0x80000000u)
                                            : __uint_as_float(~u);
        }
        __syncthreads();
    }
    float delta = 0.5f * (s_med[0] + s_med[1]);

    // step 4: total = sum (1-dm)*(A - d/2) + dm*(B + d/2)
    float acc = 0.0f;
    for (int n = tid; n < NN; n += 1024) {
        float dm = (diff[n] + diff[NN + n] + diff[2 * NN + n]) * (1.0f / 3.0f);
        acc += (1.0f - dm) * (g_inst[0][n] - 0.5f * delta)
             + dm * (g_inst[1][n] + 0.5f * delta);
    }
    sred[tid] = acc;
    __syncthreads();
    for (int o = 512; o; o >>= 1) {
        if (tid < o) sred[tid] += sred[tid + o];
        __syncthreads();
    }
    if (tid == 0) out[0] = sred[0];
}

// ---------------------------------------------------------------------------
extern "C" void kernel_launch(void* const* d_in, const int* in_sizes, int n_in,
                              void* d_out, int out_size) {
    const float* pA   = (const float*)d_in[0];  // predictions_fir [S,B,N,D]
    const float* pB   = (const float*)d_in[1];  // predictions_sec [S,B,N,D]
    const float* gt   = (const float*)d_in[2];  // gt_lane [B,L,D]
    const float* diff = (const float*)d_in[3];  // diff [S,N]
    float* out = (float*)d_out;

    int blocks_cost = 2 * SS * BB * (NN / PRI);   // 4800
    k_cost<<<blocks_cost, 320>>>(pA, pB, gt);

    k_assign<<<2 * SS * BB, 256>>>();             // 192 blocks

    k_clsmatched<<<16 + 96, 256>>>(pA, pB, gt);   // fused cls + matched

    k_final<<<1, 1024>>>(diff, out);
}

// round 7
// speedup vs baseline: 2.5646x; 1.2798x over previous
#include <cuda_runtime.h>
#include <math.h>

// Problem constants
#define SS 3       // REFINE_LAYERS
#define BB 32      // batch
#define NN 2000    // priors
#define LL 4       // max lanes
#define DD 78      // 2 + 4 + 72
#define NP 72      // num points offsets
#define PRI 80     // priors per k_cost block
#define NCHK (NN / PRI)   // 25 chunk-blocks per slice
#define NSLICE (2 * SS * BB)   // 192

// Scratch (device globals; no allocation allowed)
__device__ float    g_cost[2][SS][BB][LL][NN];
__device__ float2   g_clslog[2][SS][BB][NN];
__device__ int      g_rows[2][SS][BB][LL];
__device__ float    g_inst[2][NN];
__device__ float    g_regpart[2][SS][BB][LL];   // 768 floats
__device__ float    g_ioupart[2][SS][BB][LL];   // 768 floats
__device__ unsigned g_slice_cnt[NSLICE];        // monotonic (mod 25)
__device__ unsigned g_done;                     // monotonic (mod 28)

// ---------------------------------------------------------------------------
// Kernel 1: cost matrix + log-softmax; the last chunk-block of each slice
// (per-slice monotonic counter) then runs the greedy assignment inline.
// ---------------------------------------------------------------------------
__global__ void __launch_bounds__(320) k_cost(const float* __restrict__ pA,
                                              const float* __restrict__ pB,
                                              const float* __restrict__ gt) {
    __shared__ float sp[PRI][84];   // prediction rows, dims at [2..79]
    __shared__ float sq[LL][NP];    // gt offsets * (1/799)
    __shared__ float sraw[LL][4];   // raw gt dims 2..5
    __shared__ int   s_win;
    __shared__ float swv[10];
    __shared__ int   swi[10];
    __shared__ int   chosen[LL];
    const int tid = threadIdx.x;

    const int chunk = blockIdx.x % NCHK;
    const int slice = blockIdx.x / NCHK;     // (br,s,b) id
    int t = slice;
    const int b = t % BB;  t /= BB;
    const int s = t % SS;  const int br = t / SS;
    const int n0 = chunk * PRI;

    // gt staging (312 values)
    for (int i = tid; i < LL * DD; i += 320) {
        int l = i / DD, d = i % DD;
        float v = gt[b * LL * DD + i];
        if (d >= 6)      sq[l][d - 6]   = v * (1.0f / 799.0f);
        else if (d >= 2) sraw[l][d - 2] = v;
    }
    // prediction staging: 80 rows x 39 float2; incremental row/col stepping
    const float2* p2 = (const float2*)((br ? pB : pA)
                     + ((size_t)((s * BB + b) * NN + n0)) * DD);
    {
        int r = tid / 39;
        int c = tid - r * 39;
        #pragma unroll
        for (int it = 0; it < 10; it++) {     // 3120 float2 over 320 threads
            int i = tid + it * 320;
            if (i < PRI * DD / 2) {
                float2 v = p2[i];
                *(float2*)&sp[r][2 + 2 * c] = v;
            }
            c += 8; r += 8;                   // 320 = 8*39 + 8
            if (c >= 39) { c -= 39; r += 1; }
        }
    }
    __syncthreads();

    {
        int pr = tid >> 2, l = tid & 3;
        float p0 = sp[pr][2], p1 = sp[pr][3];
        float mx  = fmaxf(p0, p1);
        float e0  = __expf(p0 - mx), e1 = __expf(p1 - mx);
        float sum = e0 + e1;
        float lse = mx + __logf(sum);
        float score = __fdividef(e1, sum);

        float4 g4 = *(const float4*)&sp[pr][4];    // dims 2..5
        float4 t4 = *(const float4*)&sraw[l][0];
        float geo = fabsf(g4.x - t4.x) + fabsf(g4.y - t4.y)
                  + fabsf(g4.z - t4.z) + fabsf(g4.w - t4.w);

        float off = 0.0f;
        #pragma unroll
        for (int k = 0; k < NP / 4; k++) {
            float4 a = *(const float4*)&sp[pr][8 + 4 * k];
            float4 q = *(const float4*)&sq[l][4 * k];
            off += fabsf(a.x - q.x) + fabsf(a.y - q.y)
                 + fabsf(a.z - q.z) + fabsf(a.w - q.w);
        }
        g_cost[br][s][b][l][n0 + pr] = geo + off * (1.0f / 72.0f) - score;
        if (l == 0)
            g_clslog[br][s][b][n0 + pr] = make_float2(p0 - lse, p1 - lse);
    }

    // ---- per-slice gate: last chunk-block runs the greedy assignment ----
    __syncthreads();
    if (tid == 0) {
        __threadfence();
        unsigned old = atomicAdd(&g_slice_cnt[slice], 1u);
        s_win = ((old % NCHK) == NCHK - 1);
        if (s_win) __threadfence();
    }
    __syncthreads();
    if (!s_win) return;

    // greedy assignment without replacement (10 warps, 320 threads)
    const int wib = tid >> 5, lane = tid & 31;
    for (int l = 0; l < LL; l++) {
        const float* cost = &g_cost[br][s][b][l][0];
        float best = INFINITY; int bi = NN;
        for (int n = tid; n < NN; n += 320) {
            bool used = false;
            #pragma unroll
            for (int j = 0; j < 3; j++) used |= (j < l) && (chosen[j] == n);
            float v = used ? INFINITY : cost[n];
            if (v < best) { best = v; bi = n; }   // ascending n -> first idx tie
        }
        #pragma unroll
        for (int o = 16; o; o >>= 1) {
            float ov = __shfl_xor_sync(0xffffffffu, best, o);
            int   oi = __shfl_xor_sync(0xffffffffu, bi,   o);
            if (ov < best || (ov == best && oi < bi)) { best = ov; bi = oi; }
        }
        if (lane == 0) { swv[wib] = best; swi[wib] = bi; }
        __syncthreads();
        if (tid == 0) {
            float bv = swv[0]; int bix = swi[0];
            #pragma unroll
            for (int w = 1; w < 10; w++) {
                if (swv[w] < bv || (swv[w] == bv && swi[w] < bix)) {
                    bv = swv[w]; bix = swi[w];
                }
            }
            chosen[l] = bix; g_rows[br][s][b][l] = bix;
        }
        __syncthreads();
    }
}

// ---------------------------------------------------------------------------
// Kernel 2: blocks 0-3 = focal cls; blocks 4-27 = matched partials;
// last block to finish (monotonic gate) runs finalize at 1024 threads
// (parallel partial reduce, dual-rank radix-select median, weighted sum).
// ---------------------------------------------------------------------------
__global__ void __launch_bounds__(1024) k_rest(const float* __restrict__ pA,
                                               const float* __restrict__ pB,
                                               const float* __restrict__ gt,
                                               const float* __restrict__ diff,
                                               float* __restrict__ out) {
    __shared__ int      srows[SS * BB * LL];   // 384 (cls staging)
    __shared__ float    s1[1536];              // reg/iou partial staging
    __shared__ unsigned su[NN];                // radix keys
    __shared__ int      hist[512];             // dual-track histograms
    __shared__ int      s_d0, s_k0, s_d1, s_k1;
    __shared__ float    s_med[2];
    __shared__ float    sred[1024];
    __shared__ int      s_last;
    const int tid = threadIdx.x;
    const int lane = tid & 31;

    if (blockIdx.x < 4) {
        // ---- cls part: br = blockIdx>>1, n covers 2000 over 2 blocks ----
        int br = blockIdx.x >> 1;
        int n  = (blockIdx.x & 1) * 1024 + tid;

        const int* rsrc = &g_rows[br][0][0][0];
        if (tid < SS * BB * LL) srows[tid] = rsrc[tid];
        __syncthreads();

        if (n < NN) {
            const float2* lpbase = &g_clslog[br][0][0][0];
            float acc = 0.0f;
            #pragma unroll 4
            for (int sb = 0; sb < SS * BB; sb++) {
                float2 lp = lpbase[sb * NN + n];
                const int* r = &srows[sb * 4];
                bool matched = (r[0] == n) | (r[1] == n) | (r[2] == n) | (r[3] == n);
                float logpt = matched ? lp.y : lp.x;
                float pt = __expf(logpt);
                float a = matched ? 0.9f : 0.1f;
                float om = 1.0f - pt;
                acc += -a * om * om * logpt;
            }
            g_inst[br][n] = acc * (1.0f / 96.0f) * 2.0f;  // /(B*S), * CLS_W
        }
    } else {
        // ---- matched part: 32 warps/block, one (br,s,b,l) each ----
        int wib = tid >> 5;
        int id = (blockIdx.x - 4) * 32 + wib;   // [0, 768)
        int l = id % LL; int t = id / LL;
        int b = t % BB;  t /= BB;
        int s = t % SS;  int br = t / SS;

        int r = g_rows[br][s][b][l];
        const float* pm = (br ? pB : pA) + ((size_t)((s * BB + b) * NN + r)) * DD;
        const float* tg = gt + (b * LL + l) * DD;

        float sl = 0.0f;
        if (lane < 4) {
            const float scv[4] = {71.0f, 799.0f, 180.0f, 71.0f};
            float d = pm[2 + lane] * scv[lane] - tg[2 + lane] * scv[lane];
            float ad = fabsf(d);
            sl = (ad < 1.0f) ? 0.5f * d * d : ad - 0.5f;
        }
        float ovr = 0.0f, uni = 0.0f;
        #pragma unroll
        for (int jj = 0; jj < 3; jj++) {
            int j = lane + jj * 32;
            if (j < NP) {
                float rp = pm[6 + j] * 799.0f;
                float rt = tg[6 + j];
                bool inv = (rt < 0.0f) || (rt >= 800.0f);
                float o = fminf(rp + 15.0f, rt + 15.0f) - fmaxf(rp - 15.0f, rt - 15.0f);
                float u = fmaxf(rp + 15.0f, rt + 15.0f) - fminf(rp - 15.0f, rt - 15.0f);
                if (!inv) { ovr += o; uni += u; }
            }
        }
        #pragma unroll
        for (int o = 16; o; o >>= 1) {
            sl  += __shfl_xor_sync(0xffffffffu, sl,  o);
            ovr += __shfl_xor_sync(0xffffffffu, ovr, o);
            uni += __shfl_xor_sync(0xffffffffu, uni, o);
        }
        if (lane == 0) {
            float iou = ovr / (uni + 1e-9f);
            g_regpart[br][s][b][l] = (sl * 0.25f) / (float)LL;
            g_ioupart[br][s][b][l] = (1.0f - iou) / (float)LL;
        }
    }

    // ---- last-block gate (monotonic counter, no reset needed) ----
    __syncthreads();
    if (tid == 0) {
        __threadfence();
        unsigned old = atomicAdd(&g_done, 1u);
        s_last = ((old % 28u) == 27u);
        if (s_last) __threadfence();
    }
    __syncthreads();
    if (!s_last) return;

    // ================= finalize (1024 threads) ===============================
    // step 1: stage 2x768 partials into shared, 8 threads segment-sum + scatter
    if (tid < 768) {
        s1[tid]       = (&g_regpart[0][0][0][0])[tid];
        s1[768 + tid] = (&g_ioupart[0][0][0][0])[tid];
    }
    __syncthreads();
    if (tid < 2 * LL) {
        int br = tid >> 2, l = tid & 3;
        float rs = 0.0f, is = 0.0f;
        int base = br * 384 + l;
        #pragma unroll 8
        for (int sb = 0; sb < SS * BB; sb++) {
            rs += s1[base + sb * 4];
            is += s1[768 + base + sb * 4];
        }
        rs *= (1.0f / 96.0f);
        is *= (1.0f / 96.0f);
        int row = g_rows[br][SS - 1][BB - 1][l];
        g_inst[br][row] += rs * 0.5f + is * 2.0f;  // REG_W, IOU_W
    }
    __syncthreads();

    // step 2: order-preserving uint keys of x = instA - instB
    for (int n = tid; n < NN; n += 1024) {
        float x = g_inst[0][n] - g_inst[1][n];
        unsigned u = __float_as_uint(x);
        su[n] = (u & 0x80000000u) ? ~u : (u | 0x80000000u);
    }
    __syncthreads();

    // step 3: dual-rank radix select (ranks 999 & 1000 in one sweep, 4 levels)
    {
        int k0 = 999, k1 = 1000;
        unsigned pf0 = 0, pf1 = 0;
        for (int shift = 24; shift >= 0; shift -= 8) {
            unsigned mask = (shift == 24) ? 0u : (0xFFFFFFFFu << (shift + 8));
            bool eq = (pf0 == pf1);
            if (tid < 512) hist[tid] = 0;
            __syncthreads();
            #pragma unroll
            for (int it = 0; it < 2; it++) {
                int i = tid + it * 1024;
                unsigned u = (i < NN) ? su[i] : 0u;
                bool act = (i < NN);
                unsigned m = u & mask;
                int d = (int)((u >> shift) & 255);
                int bin0 = (act && m == pf0) ? d : 512;
                unsigned mm0 = __match_any_sync(0xffffffffu, bin0);
                if (bin0 < 512 && lane == (__ffs(mm0) - 1))
                    atomicAdd(&hist[bin0], __popc(mm0));
                if (!eq) {
                    int bin1 = (act && m == pf1) ? 256 + d : 512;
                    unsigned mm1 = __match_any_sync(0xffffffffu, bin1);
                    if (bin1 < 512 && lane == (__ffs(mm1) - 1))
                        atomicAdd(&hist[bin1], __popc(mm1));
                }
            }
            __syncthreads();
            if (tid < 32) {
                // track 0 (and track 1 if eq): hist[0..255]
                int base = tid * 8, ssum = 0;
                int c[8];
                #pragma unroll
                for (int j = 0; j < 8; j++) { c[j] = hist[base + j]; ssum += c[j]; }
                int run = ssum;
                #pragma unroll
                for (int o = 1; o < 32; o <<= 1) {
                    int v = __shfl_up_sync(0xffffffffu, run, o);
                    if (lane >= o) run += v;
                }
                int excl = run - ssum;
                if (k0 >= excl && k0 < run) {
                    int a2 = excl;
                    #pragma unroll
                    for (int j = 0; j < 8; j++) {
                        if (k0 < a2 + c[j]) { s_d0 = base + j; s_k0 = k0 - a2; break; }
                        a2 += c[j];
                    }
                }
                if (eq && k1 >= excl && k1 < run) {
                    int a2 = excl;
                    #pragma unroll
                    for (int j = 0; j < 8; j++) {
                        if (k1 < a2 + c[j]) { s_d1 = base + j; s_k1 = k1 - a2; break; }
                        a2 += c[j];
                    }
                }
            } else if (tid >= 32 && tid < 64 && !eq) {
                // track 1: hist[256..511]
                int l2 = tid - 32;
                int base = 256 + l2 * 8, ssum = 0;
                int c[8];
                #pragma unroll
                for (int j = 0; j < 8; j++) { c[j] = hist[base + j]; ssum += c[j]; }
                int run = ssum;
                #pragma unroll
                for (int o = 1; o < 32; o <<= 1) {
                    int v = __shfl_up_sync(0xffffffffu, run, o);
                    if (l2 >= o) run += v;
                }
                int excl = run - ssum;
                if (k1 >= excl && k1 < run) {
                    int a2 = excl;
                    #pragma unroll
                    for (int j = 0; j < 8; j++) {
                        if (k1 < a2 + c[j]) { s_d1 = base - 256 + j; s_k1 = k1 - a2; break; }
                        a2 += c[j];
                    }
                }
            }
            __syncthreads();
            pf0 |= ((unsigned)s_d0) << shift;  k0 = s_k0;
            pf1 |= ((unsigned)s_d1) << shift;  k1 = s_k1;
        }
        if (tid == 0) {
            unsigned u0 = pf0, u1 = pf1;
            s_med[0] = (u0 & 0x80000000u) ? __uint_as_float(u0 ^ 0x80000000u)
                                          : __uint_as_float(~u0);
            s_med[1] = (u1 & 0x80000000u) ? __uint_as_float(u1 ^ 0x80000000u)
                                          : __uint_as_float(~u1);
        }
        __syncthreads();
    }
    float delta = 0.5f * (s_med[0] + s_med[1]);

    // step 4: total = sum (1-dm)*(A - d/2) + dm*(B + d/2)
    float acc = 0.0f;
    for (int n = tid; n < NN; n += 1024) {
        float dm = (diff[n] + diff[NN + n] + diff[2 * NN + n]) * (1.0f / 3.0f);
        acc += (1.0f - dm) * (g_inst[0][n] - 0.5f * delta)
             + dm * (g_inst[1][n] + 0.5f * delta);
    }
    sred[tid] = acc;
    __syncthreads();
    for (int o = 512; o; o >>= 1) {
        if (tid < o) sred[tid] += sred[tid + o];
        __syncthreads();
    }
    if (tid == 0) out[0] = sred[0];
}

// ---------------------------------------------------------------------------
extern "C" void kernel_launch(void* const* d_in, const int* in_sizes, int n_in,
                              void* d_out, int out_size) {
    const float* pA   = (const float*)d_in[0];  // predictions_fir [S,B,N,D]
    const float* pB   = (const float*)d_in[1];  // predictions_sec [S,B,N,D]
    const float* gt   = (const float*)d_in[2];  // gt_lane [B,L,D]
    const float* diff = (const float*)d_in[3];  // diff [S,N]
    float* out = (float*)d_out;

    k_cost<<<NSLICE * NCHK, 320>>>(pA, pB, gt);      // 4800 blocks, assign inline
    k_rest<<<28, 1024>>>(pA, pB, gt, diff, out);     // cls+matched+finalize
}

// round 8
// speedup vs baseline: 3.0573x; 1.1921x over previous
#include <cuda_runtime.h>
#include <math.h>

// Problem constants
#define SS 3       // REFINE_LAYERS
#define BB 32      // batch
#define NN 2000    // priors
#define LL 4       // max lanes
#define DD 78      // 2 + 4 + 72
#define NP 72      // num points offsets
#define PRI 80     // priors per k_cost block
#define NCHK (NN / PRI)   // 25 chunk-blocks per slice
#define NSLICE (2 * SS * BB)   // 192
#define CLSG 8     // sb-groups for cls partials
#define SBPG (SS * BB / CLSG)  // 12 sb per group
#define NBLK2 56   // blocks in kernel 2 (32 cls + 24 matched)

// Scratch (device globals; no allocation allowed)
__device__ float    g_cost[2][SS][BB][LL][NN];
__device__ float2   g_clslog[2][SS][BB][NN];
__device__ int      g_rows[2][SS][BB][LL];
__device__ float    g_clspart[CLSG][2][NN];     // cls partial sums (fixed slots)
__device__ float    g_regpart[2][SS][BB][LL];   // 768 floats
__device__ float    g_ioupart[2][SS][BB][LL];   // 768 floats
__device__ unsigned g_slice_cnt[NSLICE];        // monotonic (mod 25)
__device__ unsigned g_done;                     // monotonic (mod 56)

// ---------------------------------------------------------------------------
// Kernel 1: cost matrix + log-softmax; the last chunk-block of each slice
// (per-slice monotonic counter) then runs the greedy assignment inline.
// ---------------------------------------------------------------------------
__global__ void __launch_bounds__(320) k_cost(const float* __restrict__ pA,
                                              const float* __restrict__ pB,
                                              const float* __restrict__ gt) {
    __shared__ float sp[PRI][84];   // prediction rows, dims at [2..79]
    __shared__ float sq[LL][NP];    // gt offsets * (1/799)
    __shared__ float sraw[LL][4];   // raw gt dims 2..5
    __shared__ int   s_win;
    __shared__ float swv[10];
    __shared__ int   swi[10];
    __shared__ int   chosen[LL];
    const int tid = threadIdx.x;

    const int chunk = blockIdx.x % NCHK;
    const int slice = blockIdx.x / NCHK;     // (br,s,b) id
    int t = slice;
    const int b = t % BB;  t /= BB;
    const int s = t % SS;  const int br = t / SS;
    const int n0 = chunk * PRI;

    // gt staging (312 values)
    for (int i = tid; i < LL * DD; i += 320) {
        int l = i / DD, d = i % DD;
        float v = gt[b * LL * DD + i];
        if (d >= 6)      sq[l][d - 6]   = v * (1.0f / 799.0f);
        else if (d >= 2) sraw[l][d - 2] = v;
    }
    // prediction staging: 80 rows x 39 float2; incremental row/col stepping
    const float2* p2 = (const float2*)((br ? pB : pA)
                     + ((size_t)((s * BB + b) * NN + n0)) * DD);
    {
        int r = tid / 39;
        int c = tid - r * 39;
        #pragma unroll
        for (int it = 0; it < 10; it++) {     // 3120 float2 over 320 threads
            int i = tid + it * 320;
            if (i < PRI * DD / 2) {
                float2 v = p2[i];
                *(float2*)&sp[r][2 + 2 * c] = v;
            }
            c += 8; r += 8;                   // 320 = 8*39 + 8
            if (c >= 39) { c -= 39; r += 1; }
        }
    }
    __syncthreads();

    {
        int pr = tid >> 2, l = tid & 3;
        float p0 = sp[pr][2], p1 = sp[pr][3];
        float mx  = fmaxf(p0, p1);
        float e0  = __expf(p0 - mx), e1 = __expf(p1 - mx);
        float sum = e0 + e1;
        float lse = mx + __logf(sum);
        float score = __fdividef(e1, sum);

        float4 g4 = *(const float4*)&sp[pr][4];    // dims 2..5
        float4 t4 = *(const float4*)&sraw[l][0];
        float geo = fabsf(g4.x - t4.x) + fabsf(g4.y - t4.y)
                  + fabsf(g4.z - t4.z) + fabsf(g4.w - t4.w);

        float off = 0.0f;
        #pragma unroll
        for (int k = 0; k < NP / 4; k++) {
            float4 a = *(const float4*)&sp[pr][8 + 4 * k];
            float4 q = *(const float4*)&sq[l][4 * k];
            off += fabsf(a.x - q.x) + fabsf(a.y - q.y)
                 + fabsf(a.z - q.z) + fabsf(a.w - q.w);
        }
        g_cost[br][s][b][l][n0 + pr] = geo + off * (1.0f / 72.0f) - score;
        if (l == 0)
            g_clslog[br][s][b][n0 + pr] = make_float2(p0 - lse, p1 - lse);
    }

    // ---- per-slice gate: last chunk-block runs the greedy assignment ----
    __syncthreads();
    if (tid == 0) {
        __threadfence();
        unsigned old = atomicAdd(&g_slice_cnt[slice], 1u);
        s_win = ((old % NCHK) == NCHK - 1);
        if (s_win) __threadfence();
    }
    __syncthreads();
    if (!s_win) return;

    // greedy assignment without replacement (10 warps, 320 threads)
    const int wib = tid >> 5, lane = tid & 31;
    for (int l = 0; l < LL; l++) {
        const float* cost = &g_cost[br][s][b][l][0];
        float best = INFINITY; int bi = NN;
        for (int n = tid; n < NN; n += 320) {
            bool used = false;
            #pragma unroll
            for (int j = 0; j < 3; j++) used |= (j < l) && (chosen[j] == n);
            float v = used ? INFINITY : cost[n];
            if (v < best) { best = v; bi = n; }   // ascending n -> first idx tie
        }
        #pragma unroll
        for (int o = 16; o; o >>= 1) {
            float ov = __shfl_xor_sync(0xffffffffu, best, o);
            int   oi = __shfl_xor_sync(0xffffffffu, bi,   o);
            if (ov < best || (ov == best && oi < bi)) { best = ov; bi = oi; }
        }
        if (lane == 0) { swv[wib] = best; swi[wib] = bi; }
        __syncthreads();
        if (tid == 0) {
            float bv = swv[0]; int bix = swi[0];
            #pragma unroll
            for (int w = 1; w < 10; w++) {
                if (swv[w] < bv || (swv[w] == bv && swi[w] < bix)) {
                    bv = swv[w]; bix = swi[w];
                }
            }
            chosen[l] = bix; g_rows[br][s][b][l] = bix;
        }
        __syncthreads();
    }
}

// ---------------------------------------------------------------------------
// Kernel 2: blocks 0-31 = focal cls partials (2 br x 2 n-halves x 8 sb-groups);
// blocks 32-55 = matched partials (32 warps each); last block (monotonic
// gate) runs finalize: inst assembly in shared, scatter, dual-rank radix
// median, weighted sum.
// ---------------------------------------------------------------------------
__global__ void __launch_bounds__(1024) k_rest(const float* __restrict__ pA,
                                               const float* __restrict__ pB,
                                               const float* __restrict__ gt,
                                               const float* __restrict__ diff,
                                               float* __restrict__ out) {
    __shared__ int      srows[SS * BB * LL];   // 384 (cls staging)
    __shared__ float    sinst[2 * NN];         // 16 KB (finalize)
    __shared__ float    s1[1536];              // reg/iou partial staging
    __shared__ unsigned su[NN];                // radix keys
    __shared__ int      hist[512];             // dual-track histograms
    __shared__ int      s_d0, s_k0, s_d1, s_k1;
    __shared__ float    s_med[2];
    __shared__ float    sred[1024];
    __shared__ int      s_last;
    const int tid = threadIdx.x;
    const int lane = tid & 31;

    if (blockIdx.x < 32) {
        // ---- cls partials: id = (br, nhalf, g) ----
        int id = blockIdx.x;
        int g  = id & 7;           // sb-group
        int nh = (id >> 3) & 1;    // n half
        int br = id >> 4;          // branch
        int n  = nh * 1024 + tid;

        const int* rsrc = &g_rows[br][0][0][0];
        if (tid < SS * BB * LL) srows[tid] = rsrc[tid];
        __syncthreads();

        if (n < NN) {
            const float2* lpbase = &g_clslog[br][0][0][0];
            float acc = 0.0f;
            int sb0 = g * SBPG;
            #pragma unroll
            for (int i = 0; i < SBPG; i++) {
                int sb = sb0 + i;
                float2 lp = lpbase[sb * NN + n];
                const int* r = &srows[sb * 4];
                bool matched = (r[0] == n) | (r[1] == n) | (r[2] == n) | (r[3] == n);
                float logpt = matched ? lp.y : lp.x;
                float pt = __expf(logpt);
                float a = matched ? 0.9f : 0.1f;
                float om = 1.0f - pt;
                acc += -a * om * om * logpt;
            }
            g_clspart[g][br][n] = acc;
        }
    } else {
        // ---- matched part: 32 warps/block, one (br,s,b,l) each ----
        int wib = tid >> 5;
        int id = (blockIdx.x - 32) * 32 + wib;   // [0, 768)
        int l = id % LL; int t = id / LL;
        int b = t % BB;  t /= BB;
        int s = t % SS;  int br = t / SS;

        int r = g_rows[br][s][b][l];
        const float* pm = (br ? pB : pA) + ((size_t)((s * BB + b) * NN + r)) * DD;
        const float* tg = gt + (b * LL + l) * DD;

        float sl = 0.0f;
        if (lane < 4) {
            const float scv[4] = {71.0f, 799.0f, 180.0f, 71.0f};
            float d = pm[2 + lane] * scv[lane] - tg[2 + lane] * scv[lane];
            float ad = fabsf(d);
            sl = (ad < 1.0f) ? 0.5f * d * d : ad - 0.5f;
        }
        float ovr = 0.0f, uni = 0.0f;
        #pragma unroll
        for (int jj = 0; jj < 3; jj++) {
            int j = lane + jj * 32;
            if (j < NP) {
                float rp = pm[6 + j] * 799.0f;
                float rt = tg[6 + j];
                bool inv = (rt < 0.0f) || (rt >= 800.0f);
                float o = fminf(rp + 15.0f, rt + 15.0f) - fmaxf(rp - 15.0f, rt - 15.0f);
                float u = fmaxf(rp + 15.0f, rt + 15.0f) - fminf(rp - 15.0f, rt - 15.0f);
                if (!inv) { ovr += o; uni += u; }
            }
        }
        #pragma unroll
        for (int o = 16; o; o >>= 1) {
            sl  += __shfl_xor_sync(0xffffffffu, sl,  o);
            ovr += __shfl_xor_sync(0xffffffffu, ovr, o);
            uni += __shfl_xor_sync(0xffffffffu, uni, o);
        }
        if (lane == 0) {
            float iou = ovr / (uni + 1e-9f);
            g_regpart[br][s][b][l] = (sl * 0.25f) / (float)LL;
            g_ioupart[br][s][b][l] = (1.0f - iou) / (float)LL;
        }
    }

    // ---- last-block gate (monotonic counter, no reset needed) ----
    __syncthreads();
    if (tid == 0) {
        __threadfence();
        unsigned old = atomicAdd(&g_done, 1u);
        s_last = ((old % (unsigned)NBLK2) == NBLK2 - 1u);
        if (s_last) __threadfence();
    }
    __syncthreads();
    if (!s_last) return;

    // ================= finalize (1024 threads) ===============================
    // step 0: assemble inst in shared from cls partials (fixed order g=0..7)
    for (int n = tid; n < NN; n += 1024) {
        float a0 = 0.0f, a1 = 0.0f;
        #pragma unroll
        for (int g = 0; g < CLSG; g++) {
            a0 += g_clspart[g][0][n];
            a1 += g_clspart[g][1][n];
        }
        sinst[n]      = a0 * (1.0f / 96.0f) * 2.0f;
        sinst[NN + n] = a1 * (1.0f / 96.0f) * 2.0f;
    }
    // step 1: stage 2x768 reg/iou partials, 8 threads segment-sum + scatter
    if (tid < 768) {
        s1[tid]       = (&g_regpart[0][0][0][0])[tid];
        s1[768 + tid] = (&g_ioupart[0][0][0][0])[tid];
    }
    __syncthreads();
    if (tid < 2 * LL) {
        int br = tid >> 2, l = tid & 3;
        float rs = 0.0f, is = 0.0f;
        int base = br * 384 + l;
        #pragma unroll 8
        for (int sb = 0; sb < SS * BB; sb++) {
            rs += s1[base + sb * 4];
            is += s1[768 + base + sb * 4];
        }
        rs *= (1.0f / 96.0f);
        is *= (1.0f / 96.0f);
        int row = g_rows[br][SS - 1][BB - 1][l];
        sinst[br * NN + row] += rs * 0.5f + is * 2.0f;  // REG_W, IOU_W
    }
    __syncthreads();

    // step 2: order-preserving uint keys of x = instA - instB
    for (int n = tid; n < NN; n += 1024) {
        float x = sinst[n] - sinst[NN + n];
        unsigned u = __float_as_uint(x);
        su[n] = (u & 0x80000000u) ? ~u : (u | 0x80000000u);
    }
    __syncthreads();

    // step 3: dual-rank radix select (ranks 999 & 1000 in one sweep, 4 levels)
    {
        int k0 = 999, k1 = 1000;
        unsigned pf0 = 0, pf1 = 0;
        for (int shift = 24; shift >= 0; shift -= 8) {
            unsigned mask = (shift == 24) ? 0u : (0xFFFFFFFFu << (shift + 8));
            bool eq = (pf0 == pf1);
            if (tid < 512) hist[tid] = 0;
            __syncthreads();
            #pragma unroll
            for (int it = 0; it < 2; it++) {
                int i = tid + it * 1024;
                unsigned u = (i < NN) ? su[i] : 0u;
                bool act = (i < NN);
                unsigned m = u & mask;
                int d = (int)((u >> shift) & 255);
                int bin0 = (act && m == pf0) ? d : 512;
                unsigned mm0 = __match_any_sync(0xffffffffu, bin0);
                if (bin0 < 512 && lane == (__ffs(mm0) - 1))
                    atomicAdd(&hist[bin0], __popc(mm0));
                if (!eq) {
                    int bin1 = (act && m == pf1) ? 256 + d : 512;
                    unsigned mm1 = __match_any_sync(0xffffffffu, bin1);
                    if (bin1 < 512 && lane == (__ffs(mm1) - 1))
                        atomicAdd(&hist[bin1], __popc(mm1));
                }
            }
            __syncthreads();
            if (tid < 32) {
                int base = tid * 8, ssum = 0;
                int c[8];
                #pragma unroll
                for (int j = 0; j < 8; j++) { c[j] = hist[base + j]; ssum += c[j]; }
                int run = ssum;
                #pragma unroll
                for (int o = 1; o < 32; o <<= 1) {
                    int v = __shfl_up_sync(0xffffffffu, run, o);
                    if (lane >= o) run += v;
                }
                int excl = run - ssum;
                if (k0 >= excl && k0 < run) {
                    int a2 = excl;
                    #pragma unroll
                    for (int j = 0; j < 8; j++) {
                        if (k0 < a2 + c[j]) { s_d0 = base + j; s_k0 = k0 - a2; break; }
                        a2 += c[j];
                    }
                }
                if (eq && k1 >= excl && k1 < run) {
                    int a2 = excl;
                    #pragma unroll
                    for (int j = 0; j < 8; j++) {
                        if (k1 < a2 + c[j]) { s_d1 = base + j; s_k1 = k1 - a2; break; }
                        a2 += c[j];
                    }
                }
            } else if (tid >= 32 && tid < 64 && !eq) {
                int l2 = tid - 32;
                int base = 256 + l2 * 8, ssum = 0;
                int c[8];
                #pragma unroll
                for (int j = 0; j < 8; j++) { c[j] = hist[base + j]; ssum += c[j]; }
                int run = ssum;
                #pragma unroll
                for (int o = 1; o < 32; o <<= 1) {
                    int v = __shfl_up_sync(0xffffffffu, run, o);
                    if (l2 >= o) run += v;
                }
                int excl = run - ssum;
                if (k1 >= excl && k1 < run) {
                    int a2 = excl;
                    #pragma unroll
                    for (int j = 0; j < 8; j++) {
                        if (k1 < a2 + c[j]) { s_d1 = base - 256 + j; s_k1 = k1 - a2; break; }
                        a2 += c[j];
                    }
                }
            }
            __syncthreads();
            pf0 |= ((unsigned)s_d0) << shift;  k0 = s_k0;
            pf1 |= ((unsigned)s_d1) << shift;  k1 = s_k1;
        }
        if (tid == 0) {
            unsigned u0 = pf0, u1 = pf1;
            s_med[0] = (u0 & 0x80000000u) ? __uint_as_float(u0 ^ 0x80000000u)
                                          : __uint_as_float(~u0);
            s_med[1] = (u1 & 0x80000000u) ? __uint_as_float(u1 ^ 0x80000000u)
                                          : __uint_as_float(~u1);
        }
        __syncthreads();
    }
    float delta = 0.5f * (s_med[0] + s_med[1]);

    // step 4: total = sum (1-dm)*(A - d/2) + dm*(B + d/2)
    float acc = 0.0f;
    for (int n = tid; n < NN; n += 1024) {
        float dm = (diff[n] + diff[NN + n] + diff[2 * NN + n]) * (1.0f / 3.0f);
        acc += (1.0f - dm) * (sinst[n] - 0.5f * delta)
             + dm * (sinst[NN + n] + 0.5f * delta);
    }
    sred[tid] = acc;
    __syncthreads();
    for (int o = 512; o; o >>= 1) {
        if (tid < o) sred[tid] += sred[tid + o];
        __syncthreads();
    }
    if (tid == 0) out[0] = sred[0];
}

// ---------------------------------------------------------------------------
extern "C" void kernel_launch(void* const* d_in, const int* in_sizes, int n_in,
                              void* d_out, int out_size) {
    const float* pA   = (const float*)d_in[0];  // predictions_fir [S,B,N,D]
    const float* pB   = (const float*)d_in[1];  // predictions_sec [S,B,N,D]
    const float* gt   = (const float*)d_in[2];  // gt_lane [B,L,D]
    const float* diff = (const float*)d_in[3];  // diff [S,N]
    float* out = (float*)d_out;

    k_cost<<<NSLICE * NCHK, 320>>>(pA, pB, gt);      // 4800 blocks, assign inline
    k_rest<<<NBLK2, 1024>>>(pA, pB, gt, diff, out);  // cls+matched+finalize
}